// round 1
// baseline (speedup 1.0000x reference)
#include <cuda_runtime.h>
#include <cstdint>

// Problem constants
#define Bb 4
#define Tt 4096
#define Dd 1024
#define HDh 64
#define Hh 16
#define Cc 64
#define nCh 64          // T / C
#define BHt 64          // B * H
#define Mrows (Bb*Tt)   // 16384

// Scratch buffers (allocation-free rule: __device__ globals)
__device__ float g_v[Bb*Tt*Dd];      // write projection, (B,T,D) layout
__device__ float g_reads[Bb*Tt*Dd];  // alpha-scaled reads, (B,T,D) layout

// ---------------------------------------------------------------------------
// SGEMM (NT): C[m,n] = sum_k A[m,k] * B[n,k]  (+ Cin[m,n] if addC)
// BM=BN=128, BK=8, 256 threads, 8x8 per thread.
// ---------------------------------------------------------------------------
__global__ __launch_bounds__(256) void sgemm_nt_kernel(
    const float* __restrict__ A,
    const float* __restrict__ B,
    const float* __restrict__ Cin,
    float* __restrict__ Cout,
    int M, int N, int K, int addC)
{
    const int BK = 8;
    __shared__ float As[BK][128];
    __shared__ float Bs[BK][128];

    int tid = threadIdx.x;
    int bm = blockIdx.y * 128;
    int bn = blockIdx.x * 128;

    int lrow = tid >> 1;          // 0..127
    int lcol = (tid & 1) << 2;    // 0 or 4

    int tx = tid & 15;            // 0..15 -> output col group
    int ty = tid >> 4;            // 0..15 -> output row group

    float acc[8][8];
#pragma unroll
    for (int i = 0; i < 8; i++)
#pragma unroll
        for (int j = 0; j < 8; j++) acc[i][j] = 0.f;

    const float* Aptr = A + (size_t)(bm + lrow) * K + lcol;
    const float* Bptr = B + (size_t)(bn + lrow) * K + lcol;

    for (int kt = 0; kt < K; kt += BK) {
        float4 av = *(const float4*)(Aptr + kt);
        float4 bv = *(const float4*)(Bptr + kt);
        As[lcol + 0][lrow] = av.x;
        As[lcol + 1][lrow] = av.y;
        As[lcol + 2][lrow] = av.z;
        As[lcol + 3][lrow] = av.w;
        Bs[lcol + 0][lrow] = bv.x;
        Bs[lcol + 1][lrow] = bv.y;
        Bs[lcol + 2][lrow] = bv.z;
        Bs[lcol + 3][lrow] = bv.w;
        __syncthreads();

#pragma unroll
        for (int k = 0; k < BK; k++) {
            float a[8], b[8];
            *(float4*)(a)     = *(const float4*)&As[k][ty * 8];
            *(float4*)(a + 4) = *(const float4*)&As[k][ty * 8 + 4];
            *(float4*)(b)     = *(const float4*)&Bs[k][tx * 8];
            *(float4*)(b + 4) = *(const float4*)&Bs[k][tx * 8 + 4];
#pragma unroll
            for (int i = 0; i < 8; i++)
#pragma unroll
                for (int j = 0; j < 8; j++)
                    acc[i][j] += a[i] * b[j];
        }
        __syncthreads();
    }

#pragma unroll
    for (int i = 0; i < 8; i++) {
        int row = bm + ty * 8 + i;
#pragma unroll
        for (int j = 0; j < 8; j += 4) {
            int col = bn + tx * 8 + j;
            float4 r;
            r.x = acc[i][j + 0];
            r.y = acc[i][j + 1];
            r.z = acc[i][j + 2];
            r.w = acc[i][j + 3];
            if (addC) {
                float4 c = *(const float4*)&Cin[(size_t)row * N + col];
                r.x += c.x; r.y += c.y; r.z += c.z; r.w += c.w;
            }
            *(float4*)&Cout[(size_t)row * N + col] = r;
        }
    }
}

// ---------------------------------------------------------------------------
// Chunked decay scan. One block per (b,h). 256 threads.
// Shared: W state (64x64), rk/wk/v chunk tiles, masked S, gamma powers.
// ---------------------------------------------------------------------------
#define SMP 65   // padded row stride (bank-conflict avoidance)
#define SCAN_SMEM ((5 * 64 * SMP + 64) * (int)sizeof(float))

__global__ __launch_bounds__(256) void scan_kernel(
    const float* __restrict__ outp,      // (B,T,D)
    const float* __restrict__ decay,     // (H,)
    const float* __restrict__ log_alpha, // (H,)
    const float* __restrict__ vbuf,      // (B,T,D)
    float* __restrict__ reads)           // (B,T,D), alpha-scaled
{
    extern __shared__ float sm[];
    float* sW  = sm;
    float* sRK = sW  + 64 * SMP;
    float* sWK = sRK + 64 * SMP;
    float* sV  = sWK + 64 * SMP;
    float* sS  = sV  + 64 * SMP;
    float* sgp = sS  + 64 * SMP;   // sgp[e] = gamma^e, e in [0,63]

    int tid = threadIdx.x;
    int bh = blockIdx.x;
    int b = bh >> 4;
    int h = bh & 15;

    float gamma = 1.f / (1.f + expf(-decay[h]));
    float alpha = expf(log_alpha[h]);
    float gC = powf(gamma, 64.f);

    if (tid < 64) sgp[tid] = powf(gamma, (float)tid);
    for (int i = tid; i < 64 * SMP; i += 256) sW[i] = 0.f;
    __syncthreads();

    const float* basep = outp + (size_t)b * Tt * Dd + h * 64;
    const float* vbase = vbuf + (size_t)b * Tt * Dd + h * 64;
    float* rbase = reads + (size_t)b * Tt * Dd + h * 64;

    int ty = tid >> 4;           // 0..15
    int tx = tid & 15;           // 0..15
    int r0 = ty * 4;             // row group (4 rows)
    int c0 = tx * 4;             // col group (4 cols)

    for (int nc = 0; nc < nCh; nc++) {
        int t0 = nc * 64;

        // ---- load rk / wk / v chunk tiles ----
#pragma unroll
        for (int i = 0; i < 4; i++) {
            int idx = tid + i * 256;      // 0..1023 (float4 index)
            int c = idx >> 4;             // row 0..63
            int d4 = (idx & 15) << 2;     // col 0..60
            const float* p = basep + (size_t)(t0 + c) * Dd + d4;
            float4 rv = *(const float4*)p;
            sRK[c * SMP + d4 + 0] = rv.x;
            sRK[c * SMP + d4 + 1] = rv.y;
            sRK[c * SMP + d4 + 2] = rv.z;
            sRK[c * SMP + d4 + 3] = rv.w;
            float4 vv = *(const float4*)(vbase + (size_t)(t0 + c) * Dd + d4);
            sV[c * SMP + d4 + 0] = vv.x;
            sV[c * SMP + d4 + 1] = vv.y;
            sV[c * SMP + d4 + 2] = vv.z;
            sV[c * SMP + d4 + 3] = vv.w;
            float4 wv;
            if (t0 + c == 0) { wv = make_float4(0.f, 0.f, 0.f, 0.f); }
            else             { wv = *(const float4*)(p - Dd); }
            sWK[c * SMP + d4 + 0] = wv.x;
            sWK[c * SMP + d4 + 1] = wv.y;
            sWK[c * SMP + d4 + 2] = wv.z;
            sWK[c * SMP + d4 + 3] = wv.w;
        }
        __syncthreads();

        // ---- S[c,k] = (sum_d rk[c,d]*wk[k,d]) * mask(c,k) ----
        {
            float acc[4][4];
#pragma unroll
            for (int i = 0; i < 4; i++)
#pragma unroll
                for (int j = 0; j < 4; j++) acc[i][j] = 0.f;
#pragma unroll 8
            for (int d = 0; d < 64; d++) {
                float a[4], w[4];
#pragma unroll
                for (int i = 0; i < 4; i++) a[i] = sRK[(r0 + i) * SMP + d];
#pragma unroll
                for (int j = 0; j < 4; j++) w[j] = sWK[(c0 + j) * SMP + d];
#pragma unroll
                for (int i = 0; i < 4; i++)
#pragma unroll
                    for (int j = 0; j < 4; j++)
                        acc[i][j] += a[i] * w[j];
            }
#pragma unroll
            for (int i = 0; i < 4; i++) {
                int cc = r0 + i;
#pragma unroll
                for (int j = 0; j < 4; j++) {
                    int kk = c0 + j;
                    float m = (cc > kk) ? sgp[cc - 1 - kk] : 0.f;
                    sS[cc * SMP + kk] = acc[i][j] * m;
                }
            }
        }
        __syncthreads();

        // ---- read[c,d] = gp[c]*sum_j W[d,j]*rk[c,j] + sum_k S[c,k]*v[k,d] ----
        {
            float r[4][4];
#pragma unroll
            for (int i = 0; i < 4; i++)
#pragma unroll
                for (int j = 0; j < 4; j++) r[i][j] = 0.f;
            // inter: W[d][j] * rk[c][j]
#pragma unroll 8
            for (int j = 0; j < 64; j++) {
                float a[4], w[4];
#pragma unroll
                for (int i = 0; i < 4; i++) a[i] = sRK[(r0 + i) * SMP + j];
#pragma unroll
                for (int jd = 0; jd < 4; jd++) w[jd] = sW[(c0 + jd) * SMP + j];
#pragma unroll
                for (int i = 0; i < 4; i++)
#pragma unroll
                    for (int jd = 0; jd < 4; jd++)
                        r[i][jd] += a[i] * w[jd];
            }
#pragma unroll
            for (int i = 0; i < 4; i++) {
                float gp = sgp[r0 + i];
#pragma unroll
                for (int j = 0; j < 4; j++) r[i][j] *= gp;
            }
            // intra: S[c][k] * v[k][d]
#pragma unroll 8
            for (int k = 0; k < 64; k++) {
                float s[4], vv[4];
#pragma unroll
                for (int i = 0; i < 4; i++) s[i] = sS[(r0 + i) * SMP + k];
#pragma unroll
                for (int j = 0; j < 4; j++) vv[j] = sV[k * SMP + c0 + j];
#pragma unroll
                for (int i = 0; i < 4; i++)
#pragma unroll
                    for (int j = 0; j < 4; j++)
                        r[i][j] += s[i] * vv[j];
            }
#pragma unroll
            for (int i = 0; i < 4; i++) {
                float* wp = rbase + (size_t)(t0 + r0 + i) * Dd + c0;
                float4 v4;
                v4.x = alpha * r[i][0];
                v4.y = alpha * r[i][1];
                v4.z = alpha * r[i][2];
                v4.w = alpha * r[i][3];
                *(float4*)wp = v4;
            }
        }
        __syncthreads();   // protect sW reads before update

        // ---- W[i,j] = gC*W[i,j] + sum_c (v[c,i]*gw[c]) * wk[c,j] ----
        {
            float wacc[4][4];
#pragma unroll
            for (int i = 0; i < 4; i++)
#pragma unroll
                for (int j = 0; j < 4; j++)
                    wacc[i][j] = gC * sW[(r0 + i) * SMP + c0 + j];
#pragma unroll 8
            for (int c = 0; c < 64; c++) {
                float gw = sgp[63 - c];
                float a[4], w[4];
#pragma unroll
                for (int i = 0; i < 4; i++) a[i] = sV[c * SMP + r0 + i] * gw;
#pragma unroll
                for (int j = 0; j < 4; j++) w[j] = sWK[c * SMP + c0 + j];
#pragma unroll
                for (int i = 0; i < 4; i++)
#pragma unroll
                    for (int j = 0; j < 4; j++)
                        wacc[i][j] += a[i] * w[j];
            }
#pragma unroll
            for (int i = 0; i < 4; i++)
#pragma unroll
                for (int j = 0; j < 4; j++)
                    sW[(r0 + i) * SMP + c0 + j] = wacc[i][j];
        }
        __syncthreads();   // protect tiles before next load
    }
}

// ---------------------------------------------------------------------------
extern "C" void kernel_launch(void* const* d_in, const int* in_sizes, int n_in,
                              void* d_out, int out_size)
{
    const float* outp      = (const float*)d_in[0];  // (B,T,D)
    const float* W_write   = (const float*)d_in[1];  // (D,D)
    const float* W_read    = (const float*)d_in[2];  // (D,D)
    const float* decay     = (const float*)d_in[3];  // (H,)
    const float* log_alpha = (const float*)d_in[4];  // (H,)
    float* result = (float*)d_out;

    float* vptr = nullptr;
    float* rptr = nullptr;
    cudaGetSymbolAddress((void**)&vptr, g_v);
    cudaGetSymbolAddress((void**)&rptr, g_reads);

    dim3 gemm_grid(Dd / 128, Mrows / 128);   // (8, 128)

    // GEMM1: v = out @ W_write^T
    sgemm_nt_kernel<<<gemm_grid, 256>>>(outp, W_write, nullptr, vptr,
                                        Mrows, Dd, Dd, 0);

    // Scan: per-(b,h) sequential chunk recurrence
    cudaFuncSetAttribute(scan_kernel,
                         cudaFuncAttributeMaxDynamicSharedMemorySize,
                         SCAN_SMEM);
    scan_kernel<<<BHt, 256, SCAN_SMEM>>>(outp, decay, log_alpha, vptr, rptr);

    // GEMM2: result = out + reads @ W_read^T
    sgemm_nt_kernel<<<gemm_grid, 256>>>(rptr, W_read, outp, result,
                                        Mrows, Dd, Dd, 1);
}

// round 2
// speedup vs baseline: 2.8500x; 2.8500x over previous
#include <cuda_runtime.h>
#include <cstdint>

// Problem constants
#define Bb 4
#define Tt 4096
#define Dd 1024
#define Hh 16
#define Cc 64
#define nCh 64          // T / C
#define BHt 64          // B * H
#define Mrows (Bb*Tt)   // 16384

// Scratch (allocation-free rule: __device__ globals)
__device__ float g_v[Bb*Tt*Dd];        // write projection (B,T,D)
__device__ float g_reads[Bb*Tt*Dd];    // alpha-scaled reads (B,T,D)
__device__ float g_ZW[BHt*nCh*64*64];  // chunk increments -> W states (in-place)

extern __shared__ float gsm[];

// ===========================================================================
// TF32 tensor-core GEMM (NT): C[m,n] = sum_k A[m,k]*B[n,k] (+ Cin[m,n])
// BM=BN=128, BK=32, 256 threads = 8 warps (2 in M x 4 in N), warp tile 64x32,
// mma.sync.m16n8k8.tf32, cp.async double-buffered.
// ===========================================================================
#define GBK 32
#define ASTR 36   // smem row stride in floats (conflict-free frag loads)

__device__ __forceinline__ uint32_t f2tf32(float f) {
    uint32_t u;
    asm("cvt.rna.tf32.f32 %0, %1;" : "=r"(u) : "f"(f));
    return u;
}

__device__ __forceinline__ void cp16(float* sdst, const float* gsrc) {
    unsigned s = (unsigned)__cvta_generic_to_shared(sdst);
    asm volatile("cp.async.ca.shared.global [%0], [%1], 16;" :: "r"(s), "l"(gsrc));
}

__global__ __launch_bounds__(256) void tf32_gemm_nt(
    const float* __restrict__ A,
    const float* __restrict__ B,
    const float* __restrict__ Cin,
    float* __restrict__ Cout,
    int M, int N, int K, int addC)
{
    float* As = gsm;                  // [2][128][ASTR]
    float* Bs = gsm + 2*128*ASTR;     // [2][128][ASTR]

    const int tid  = threadIdx.x;
    const int lane = tid & 31;
    const int w    = tid >> 5;
    const int wm   = w >> 2;          // 0..1
    const int wn   = w & 3;           // 0..3
    const int gid  = lane >> 2;       // 0..7
    const int t4   = lane & 3;        // 0..3

    const int bm = blockIdx.y * 128;
    const int bn = blockIdx.x * 128;

    // copy indexing: thread covers rows (tid>>3)+32*i, col group (tid&7)*4
    const int cr  = tid >> 3;         // 0..31
    const int cc4 = (tid & 7) * 4;    // 0..28

    float acc[4][4][4];
#pragma unroll
    for (int i = 0; i < 4; i++)
#pragma unroll
        for (int j = 0; j < 4; j++)
#pragma unroll
            for (int q = 0; q < 4; q++) acc[i][j][q] = 0.f;

    const int NIT = K / GBK;

    auto copy_tile = [&](int it, int buf) {
        const int kt = it * GBK;
        float* ad = As + buf*128*ASTR;
        float* bd = Bs + buf*128*ASTR;
#pragma unroll
        for (int i = 0; i < 4; i++) {
            int row = cr + i*32;
            cp16(ad + row*ASTR + cc4, A + (size_t)(bm + row)*K + kt + cc4);
            cp16(bd + row*ASTR + cc4, B + (size_t)(bn + row)*K + kt + cc4);
        }
    };

    copy_tile(0, 0);
    asm volatile("cp.async.commit_group;");

    for (int it = 0; it < NIT; it++) {
        if (it + 1 < NIT) copy_tile(it + 1, (it + 1) & 1);
        asm volatile("cp.async.commit_group;");
        asm volatile("cp.async.wait_group 1;");
        __syncthreads();

        const float* ab = As + (it & 1)*128*ASTR;
        const float* bb = Bs + (it & 1)*128*ASTR;

#pragma unroll
        for (int kk = 0; kk < 4; kk++) {
            const int k0 = kk * 8;
            uint32_t af[4][4], bf[4][2];
#pragma unroll
            for (int i = 0; i < 4; i++) {
                int r = wm*64 + i*16 + gid;
                af[i][0] = f2tf32(ab[(r    )*ASTR + k0 + t4    ]);
                af[i][1] = f2tf32(ab[(r + 8)*ASTR + k0 + t4    ]);
                af[i][2] = f2tf32(ab[(r    )*ASTR + k0 + t4 + 4]);
                af[i][3] = f2tf32(ab[(r + 8)*ASTR + k0 + t4 + 4]);
            }
#pragma unroll
            for (int j = 0; j < 4; j++) {
                int r = wn*32 + j*8 + gid;
                bf[j][0] = f2tf32(bb[r*ASTR + k0 + t4    ]);
                bf[j][1] = f2tf32(bb[r*ASTR + k0 + t4 + 4]);
            }
#pragma unroll
            for (int i = 0; i < 4; i++)
#pragma unroll
                for (int j = 0; j < 4; j++) {
                    asm volatile(
                        "mma.sync.aligned.m16n8k8.row.col.f32.tf32.tf32.f32 "
                        "{%0,%1,%2,%3}, {%4,%5,%6,%7}, {%8,%9}, {%0,%1,%2,%3};"
                        : "+f"(acc[i][j][0]), "+f"(acc[i][j][1]),
                          "+f"(acc[i][j][2]), "+f"(acc[i][j][3])
                        : "r"(af[i][0]), "r"(af[i][1]), "r"(af[i][2]), "r"(af[i][3]),
                          "r"(bf[j][0]), "r"(bf[j][1]));
                }
        }
        __syncthreads();
    }

    // epilogue
#pragma unroll
    for (int i = 0; i < 4; i++) {
        int row = bm + wm*64 + i*16 + gid;
#pragma unroll
        for (int j = 0; j < 4; j++) {
            int col = bn + wn*32 + j*8 + t4*2;
            float2 r01 = make_float2(acc[i][j][0], acc[i][j][1]);
            float2 r23 = make_float2(acc[i][j][2], acc[i][j][3]);
            if (addC) {
                float2 c01 = *(const float2*)&Cin[(size_t)row*N + col];
                float2 c23 = *(const float2*)&Cin[(size_t)(row + 8)*N + col];
                r01.x += c01.x; r01.y += c01.y;
                r23.x += c23.x; r23.y += c23.y;
            }
            *(float2*)&Cout[(size_t)row*N + col]       = r01;
            *(float2*)&Cout[(size_t)(row + 8)*N + col] = r23;
        }
    }
}

// ===========================================================================
// Scan phase A (fully parallel over bh x chunk): per chunk compute
//   S = (rk @ wk^T) * mask, intra = S @ v  (write alpha*intra to reads)
//   Z[i,j] = sum_c v[c,i]*g_w[c]*wk[c,j]   (write to ZW)
// ===========================================================================
#define SMP 65
#define A_SMEM ((4*64*SMP + 64) * (int)sizeof(float))
#define C_SMEM ((2*64*SMP + 64) * (int)sizeof(float))

__global__ __launch_bounds__(256) void scan_phaseA(
    const float* __restrict__ outp,
    const float* __restrict__ vbuf,
    const float* __restrict__ decay,
    const float* __restrict__ log_alpha,
    float* __restrict__ reads,
    float* __restrict__ ZW)
{
    float* sRK = gsm;
    float* sWK = sRK + 64*SMP;
    float* sV  = sWK + 64*SMP;
    float* sS  = sV  + 64*SMP;
    float* sgp = sS  + 64*SMP;

    const int tid = threadIdx.x;
    const int chunk = blockIdx.x;
    const int bh = blockIdx.y;
    const int b = bh >> 4, h = bh & 15;

    const float gamma = 1.f / (1.f + expf(-decay[h]));
    const float alpha = expf(log_alpha[h]);
    if (tid < 64) sgp[tid] = powf(gamma, (float)tid);

    const int t0 = chunk * 64;
    const float* basep = outp + (size_t)b*Tt*Dd + h*64;
    const float* vbase = vbuf + (size_t)b*Tt*Dd + h*64;

    // load rk/wk/v tiles
#pragma unroll
    for (int i = 0; i < 4; i++) {
        int idx = tid + i*256;
        int c = idx >> 4;
        int d4 = (idx & 15) << 2;
        const float* p = basep + (size_t)(t0 + c)*Dd + d4;
        float4 rv = *(const float4*)p;
        sRK[c*SMP + d4+0] = rv.x; sRK[c*SMP + d4+1] = rv.y;
        sRK[c*SMP + d4+2] = rv.z; sRK[c*SMP + d4+3] = rv.w;
        float4 vv = *(const float4*)(vbase + (size_t)(t0 + c)*Dd + d4);
        sV[c*SMP + d4+0] = vv.x; sV[c*SMP + d4+1] = vv.y;
        sV[c*SMP + d4+2] = vv.z; sV[c*SMP + d4+3] = vv.w;
        float4 wv;
        if (t0 + c == 0) wv = make_float4(0.f,0.f,0.f,0.f);
        else             wv = *(const float4*)(p - Dd);
        sWK[c*SMP + d4+0] = wv.x; sWK[c*SMP + d4+1] = wv.y;
        sWK[c*SMP + d4+2] = wv.z; sWK[c*SMP + d4+3] = wv.w;
    }
    __syncthreads();

    const int ty = tid >> 4, tx = tid & 15;
    const int r0 = ty*4, c0 = tx*4;

    // ---- S = masked rk @ wk^T ----
    {
        float a4[4][4];
#pragma unroll
        for (int i = 0; i < 4; i++)
#pragma unroll
            for (int j = 0; j < 4; j++) a4[i][j] = 0.f;
#pragma unroll 8
        for (int d = 0; d < 64; d++) {
            float a[4], wv[4];
#pragma unroll
            for (int i = 0; i < 4; i++) a[i] = sRK[(r0+i)*SMP + d];
#pragma unroll
            for (int j = 0; j < 4; j++) wv[j] = sWK[(c0+j)*SMP + d];
#pragma unroll
            for (int i = 0; i < 4; i++)
#pragma unroll
                for (int j = 0; j < 4; j++) a4[i][j] += a[i]*wv[j];
        }
#pragma unroll
        for (int i = 0; i < 4; i++) {
            int cc = r0 + i;
#pragma unroll
            for (int j = 0; j < 4; j++) {
                int kk = c0 + j;
                float m = (cc > kk) ? sgp[cc - 1 - kk] : 0.f;
                sS[cc*SMP + kk] = a4[i][j] * m;
            }
        }
    }

    // ---- Z[i,j] = sum_c v[c,i]*g_w[c]*wk[c,j]  (independent of sS) ----
    {
        float z[4][4];
#pragma unroll
        for (int i = 0; i < 4; i++)
#pragma unroll
            for (int j = 0; j < 4; j++) z[i][j] = 0.f;
#pragma unroll 8
        for (int c = 0; c < 64; c++) {
            float gw = sgp[63 - c];
            float a[4], wv[4];
#pragma unroll
            for (int i = 0; i < 4; i++) a[i] = sV[c*SMP + r0 + i] * gw;
#pragma unroll
            for (int j = 0; j < 4; j++) wv[j] = sWK[c*SMP + c0 + j];
#pragma unroll
            for (int i = 0; i < 4; i++)
#pragma unroll
                for (int j = 0; j < 4; j++) z[i][j] += a[i]*wv[j];
        }
        float* zbase = ZW + ((size_t)bh*nCh + chunk)*4096;
#pragma unroll
        for (int i = 0; i < 4; i++) {
            float4 v4 = make_float4(z[i][0], z[i][1], z[i][2], z[i][3]);
            *(float4*)&zbase[(r0+i)*64 + c0] = v4;
        }
    }
    __syncthreads();

    // ---- intra = S @ v -> reads (alpha-scaled) ----
    {
        float r[4][4];
#pragma unroll
        for (int i = 0; i < 4; i++)
#pragma unroll
            for (int j = 0; j < 4; j++) r[i][j] = 0.f;
#pragma unroll 8
        for (int k = 0; k < 64; k++) {
            float s[4], vv[4];
#pragma unroll
            for (int i = 0; i < 4; i++) s[i] = sS[(r0+i)*SMP + k];
#pragma unroll
            for (int j = 0; j < 4; j++) vv[j] = sV[k*SMP + c0 + j];
#pragma unroll
            for (int i = 0; i < 4; i++)
#pragma unroll
                for (int j = 0; j < 4; j++) r[i][j] += s[i]*vv[j];
        }
        float* rbase = reads + (size_t)b*Tt*Dd + h*64;
#pragma unroll
        for (int i = 0; i < 4; i++) {
            float4 v4 = make_float4(alpha*r[i][0], alpha*r[i][1],
                                    alpha*r[i][2], alpha*r[i][3]);
            *(float4*)&rbase[(size_t)(t0 + r0 + i)*Dd + c0] = v4;
        }
    }
}

// ===========================================================================
// Scan phase B: in-place exclusive decayed prefix over chunks:
//   W_n = gC*W_{n-1} + Z_{n-1},  W_0 = 0   (ZW[n] := W_n)
// ===========================================================================
__global__ __launch_bounds__(256) void scan_phaseB(
    const float* __restrict__ decay, float* __restrict__ ZW)
{
    const int bh = blockIdx.y, h = bh & 15;
    const int e = blockIdx.x * 256 + threadIdx.x;   // 0..4095
    const float gamma = 1.f / (1.f + expf(-decay[h]));
    const float gC = powf(gamma, 64.f);
    float wacc = 0.f;
    size_t base = (size_t)bh*nCh*4096 + e;
#pragma unroll 4
    for (int n = 0; n < nCh; n++) {
        float z = ZW[base + (size_t)n*4096];
        ZW[base + (size_t)n*4096] = wacc;
        wacc = gC*wacc + z;
    }
}

// ===========================================================================
// Scan phase C (parallel): inter[c,i] = g_p[c] * sum_j rk[c,j]*W_n[i,j]
//   reads += alpha * inter
// ===========================================================================
__global__ __launch_bounds__(256) void scan_phaseC(
    const float* __restrict__ outp,
    const float* __restrict__ decay,
    const float* __restrict__ log_alpha,
    const float* __restrict__ ZW,
    float* __restrict__ reads)
{
    float* sRK = gsm;
    float* sW  = sRK + 64*SMP;
    float* sgp = sW  + 64*SMP;

    const int tid = threadIdx.x;
    const int chunk = blockIdx.x;
    const int bh = blockIdx.y;
    const int b = bh >> 4, h = bh & 15;

    const float gamma = 1.f / (1.f + expf(-decay[h]));
    const float alpha = expf(log_alpha[h]);
    if (tid < 64) sgp[tid] = powf(gamma, (float)tid);

    const int t0 = chunk * 64;
    const float* basep = outp + (size_t)b*Tt*Dd + h*64;
    const float* wsrc = ZW + ((size_t)bh*nCh + chunk)*4096;

#pragma unroll
    for (int i = 0; i < 4; i++) {
        int idx = tid + i*256;
        int c = idx >> 4;
        int d4 = (idx & 15) << 2;
        float4 rv = *(const float4*)(basep + (size_t)(t0 + c)*Dd + d4);
        sRK[c*SMP + d4+0] = rv.x; sRK[c*SMP + d4+1] = rv.y;
        sRK[c*SMP + d4+2] = rv.z; sRK[c*SMP + d4+3] = rv.w;
        float4 wv = *(const float4*)(wsrc + c*64 + d4);
        sW[c*SMP + d4+0] = wv.x; sW[c*SMP + d4+1] = wv.y;
        sW[c*SMP + d4+2] = wv.z; sW[c*SMP + d4+3] = wv.w;
    }
    __syncthreads();

    const int ty = tid >> 4, tx = tid & 15;
    const int r0 = ty*4, c0 = tx*4;

    float r[4][4];
#pragma unroll
    for (int i = 0; i < 4; i++)
#pragma unroll
        for (int j = 0; j < 4; j++) r[i][j] = 0.f;
#pragma unroll 8
    for (int j = 0; j < 64; j++) {
        float a[4], wv[4];
#pragma unroll
        for (int i = 0; i < 4; i++) a[i] = sRK[(r0+i)*SMP + j];
#pragma unroll
        for (int jd = 0; jd < 4; jd++) wv[jd] = sW[(c0+jd)*SMP + j];
#pragma unroll
        for (int i = 0; i < 4; i++)
#pragma unroll
            for (int jd = 0; jd < 4; jd++) r[i][jd] += a[i]*wv[jd];
    }

    float* rbase = reads + (size_t)b*Tt*Dd + h*64;
#pragma unroll
    for (int i = 0; i < 4; i++) {
        float gp = alpha * sgp[r0 + i];
        float* wp = &rbase[(size_t)(t0 + r0 + i)*Dd + c0];
        float4 cur = *(float4*)wp;
        cur.x += gp * r[i][0];
        cur.y += gp * r[i][1];
        cur.z += gp * r[i][2];
        cur.w += gp * r[i][3];
        *(float4*)wp = cur;
    }
}

// ===========================================================================
extern "C" void kernel_launch(void* const* d_in, const int* in_sizes, int n_in,
                              void* d_out, int out_size)
{
    const float* outp      = (const float*)d_in[0];
    const float* W_write   = (const float*)d_in[1];
    const float* W_read    = (const float*)d_in[2];
    const float* decay     = (const float*)d_in[3];
    const float* log_alpha = (const float*)d_in[4];
    float* result = (float*)d_out;

    float* vptr = nullptr; float* rptr = nullptr; float* zwptr = nullptr;
    cudaGetSymbolAddress((void**)&vptr, g_v);
    cudaGetSymbolAddress((void**)&rptr, g_reads);
    cudaGetSymbolAddress((void**)&zwptr, g_ZW);

    const int GEMM_SMEM = 2*2*128*ASTR*(int)sizeof(float);   // 73728
    cudaFuncSetAttribute(tf32_gemm_nt,
        cudaFuncAttributeMaxDynamicSharedMemorySize, GEMM_SMEM);
    cudaFuncSetAttribute(scan_phaseA,
        cudaFuncAttributeMaxDynamicSharedMemorySize, A_SMEM);
    cudaFuncSetAttribute(scan_phaseC,
        cudaFuncAttributeMaxDynamicSharedMemorySize, C_SMEM);

    dim3 gemm_grid(Dd/128, Mrows/128);   // (8, 128)

    // GEMM1: v = out @ W_write^T
    tf32_gemm_nt<<<gemm_grid, 256, GEMM_SMEM>>>(outp, W_write, nullptr, vptr,
                                                Mrows, Dd, Dd, 0);
    // Scan phases
    scan_phaseA<<<dim3(nCh, BHt), 256, A_SMEM>>>(outp, vptr, decay, log_alpha,
                                                 rptr, zwptr);
    scan_phaseB<<<dim3(16, BHt), 256>>>(decay, zwptr);
    scan_phaseC<<<dim3(nCh, BHt), 256, C_SMEM>>>(outp, decay, log_alpha,
                                                 zwptr, rptr);
    // GEMM2: result = out + reads @ W_read^T
    tf32_gemm_nt<<<gemm_grid, 256, GEMM_SMEM>>>(rptr, W_read, outp, result,
                                                Mrows, Dd, Dd, 1);
}

// round 3
// speedup vs baseline: 3.7878x; 1.3290x over previous
#include <cuda_runtime.h>
#include <cuda_fp16.h>
#include <cstdint>

// Problem constants
#define Bb 4
#define Tt 4096
#define Dd 1024
#define Hh 16
#define Cc 64
#define nCh 64
#define BHt 64
#define Mrows (Bb*Tt)   // 16384

// Scratch (__device__ globals per allocation rules)
__device__ float  g_v[Bb*Tt*Dd];         // write projection fp32 (scan consumes)
__device__ float  g_intra[Bb*Tt*Dd];     // alpha*intra fp32
__device__ float  g_ZW[BHt*nCh*64*64];   // chunk increments -> W states
__device__ __half g_out_h[Bb*Tt*Dd];     // fp16 copy of input
__device__ __half g_Ww_h[Dd*Dd];
__device__ __half g_Wr_h[Dd*Dd];
__device__ __half g_reads_h[Bb*Tt*Dd];   // final reads fp16 (GEMM2 A)

extern __shared__ float gsm[];

// ===========================================================================
// fp32 -> fp16 conversion (vectorized)
// ===========================================================================
__global__ __launch_bounds__(256) void cvt_f2h(
    const float4* __restrict__ src, __half2* __restrict__ dst, int n4)
{
    int i = blockIdx.x * blockDim.x + threadIdx.x;
    if (i < n4) {
        float4 v = src[i];
        dst[i*2]   = __floats2half2_rn(v.x, v.y);
        dst[i*2+1] = __floats2half2_rn(v.z, v.w);
    }
}

// ===========================================================================
// fp16 tensor-core GEMM (NT): C[m,n]=sum_k A[m,k]*B[n,k] (+Cin), f32 accum.
// BM=BN=128, BK=32, 256 thr = 8 warps (2x4), warp tile 64x32,
// mma.m16n8k16, ldmatrix.x4, 3-stage cp.async. smem stride 40 halves (80B).
// ===========================================================================
#define HSTR 40
#define HSTAGE (128*HSTR)            // halves per matrix per stage
#define GEMM_SMEM (3*2*HSTAGE*(int)sizeof(__half))   // 61440 B

__device__ __forceinline__ void cp16g(void* sdst, const void* gsrc) {
    unsigned s = (unsigned)__cvta_generic_to_shared(sdst);
    asm volatile("cp.async.ca.shared.global [%0], [%1], 16;" :: "r"(s), "l"(gsrc));
}

__global__ __launch_bounds__(256, 2) void h16_gemm_nt(
    const __half* __restrict__ A,
    const __half* __restrict__ B,
    const float* __restrict__ Cin,
    float* __restrict__ Cout,
    int M, int N, int K, int addC)
{
    __half* hsm = (__half*)gsm;
    const int tid  = threadIdx.x;
    const int lane = tid & 31;
    const int w    = tid >> 5;
    const int wm   = w >> 2;        // 0..1
    const int wn   = w & 3;         // 0..3
    const int gid  = lane >> 2;     // 0..7
    const int t4   = lane & 3;      // 0..3

    const int bm = blockIdx.y * 128;
    const int bn = blockIdx.x * 128;

    const uint32_t sb = (uint32_t)__cvta_generic_to_shared(hsm);

    float acc[4][4][4];
#pragma unroll
    for (int i = 0; i < 4; i++)
#pragma unroll
        for (int j = 0; j < 4; j++)
#pragma unroll
            for (int q = 0; q < 4; q++) acc[i][j][q] = 0.f;

    const int NIT = K / 32;

    auto copy_stage = [&](int it, int st) {
        const int kt = it * 32;
        __half* ad = hsm + st * HSTAGE;
        __half* bd = hsm + 3 * HSTAGE + st * HSTAGE;
#pragma unroll
        for (int i = 0; i < 2; i++) {
            int ch = tid + i * 256;         // 0..511
            int r  = ch >> 2;               // 0..127
            int c  = (ch & 3) * 8;          // 0,8,16,24 halves
            cp16g(ad + r * HSTR + c, A + (size_t)(bm + r) * K + kt + c);
            cp16g(bd + r * HSTR + c, B + (size_t)(bn + r) * K + kt + c);
        }
    };

    copy_stage(0, 0);
    asm volatile("cp.async.commit_group;");
    copy_stage(1, 1);
    asm volatile("cp.async.commit_group;");

    const int lrow = lane & 15;             // ldmatrix row within 16
    const int lcol = (lane >> 4) * 8;       // 0 or 8 (k half)

    for (int it = 0; it < NIT; it++) {
        asm volatile("cp.async.wait_group 1;");
        __syncthreads();
        const int st = it % 3;
        const uint32_t abase = sb + (st * HSTAGE) * 2;
        const uint32_t bbase = sb + (3 * HSTAGE + st * HSTAGE) * 2;

#pragma unroll
        for (int kk = 0; kk < 2; kk++) {
            const int k0 = kk * 16;
            uint32_t af[4][4], bf[4][2];
#pragma unroll
            for (int i = 0; i < 4; i++) {
                uint32_t ad = abase + ((wm*64 + i*16 + lrow) * HSTR + k0 + lcol) * 2;
                asm volatile(
                    "ldmatrix.sync.aligned.m8n8.x4.shared.b16 {%0,%1,%2,%3}, [%4];"
                    : "=r"(af[i][0]), "=r"(af[i][1]), "=r"(af[i][2]), "=r"(af[i][3])
                    : "r"(ad));
            }
#pragma unroll
            for (int p = 0; p < 2; p++) {
                uint32_t bd = bbase + ((wn*32 + p*16 + lrow) * HSTR + k0 + lcol) * 2;
                uint32_t r0, r1, r2, r3;
                asm volatile(
                    "ldmatrix.sync.aligned.m8n8.x4.shared.b16 {%0,%1,%2,%3}, [%4];"
                    : "=r"(r0), "=r"(r1), "=r"(r2), "=r"(r3)
                    : "r"(bd));
                bf[2*p  ][0] = r0; bf[2*p+1][0] = r1;
                bf[2*p  ][1] = r2; bf[2*p+1][1] = r3;
            }
#pragma unroll
            for (int i = 0; i < 4; i++)
#pragma unroll
                for (int j = 0; j < 4; j++) {
                    asm volatile(
                        "mma.sync.aligned.m16n8k16.row.col.f32.f16.f16.f32 "
                        "{%0,%1,%2,%3}, {%4,%5,%6,%7}, {%8,%9}, {%0,%1,%2,%3};"
                        : "+f"(acc[i][j][0]), "+f"(acc[i][j][1]),
                          "+f"(acc[i][j][2]), "+f"(acc[i][j][3])
                        : "r"(af[i][0]), "r"(af[i][1]), "r"(af[i][2]), "r"(af[i][3]),
                          "r"(bf[j][0]), "r"(bf[j][1]));
                }
        }
        if (it + 2 < NIT) copy_stage(it + 2, (it + 2) % 3);
        asm volatile("cp.async.commit_group;");
    }

    // epilogue
#pragma unroll
    for (int i = 0; i < 4; i++) {
        int row = bm + wm*64 + i*16 + gid;
#pragma unroll
        for (int j = 0; j < 4; j++) {
            int col = bn + wn*32 + j*8 + t4*2;
            float2 r01 = make_float2(acc[i][j][0], acc[i][j][1]);
            float2 r23 = make_float2(acc[i][j][2], acc[i][j][3]);
            if (addC) {
                float2 c01 = *(const float2*)&Cin[(size_t)row*N + col];
                float2 c23 = *(const float2*)&Cin[(size_t)(row+8)*N + col];
                r01.x += c01.x; r01.y += c01.y;
                r23.x += c23.x; r23.y += c23.y;
            }
            *(float2*)&Cout[(size_t)row*N + col]     = r01;
            *(float2*)&Cout[(size_t)(row+8)*N + col] = r23;
        }
    }
}

// ===========================================================================
// Scan phase A: per (bh, chunk): S=(rk@wk^T)*mask, intra=alpha*S@v -> g_intra,
// Z = (v*g_w)^T @ wk -> ZW
// ===========================================================================
#define SMP 65
#define A_SMEM ((4*64*SMP + 64) * (int)sizeof(float))
#define C_SMEM ((2*64*SMP + 64) * (int)sizeof(float))

__global__ __launch_bounds__(256) void scan_phaseA(
    const float* __restrict__ outp,
    const float* __restrict__ vbuf,
    const float* __restrict__ decay,
    const float* __restrict__ log_alpha,
    float* __restrict__ intra,
    float* __restrict__ ZW)
{
    float* sRK = gsm;
    float* sWK = sRK + 64*SMP;
    float* sV  = sWK + 64*SMP;
    float* sS  = sV  + 64*SMP;
    float* sgp = sS  + 64*SMP;

    const int tid = threadIdx.x;
    const int chunk = blockIdx.x;
    const int bh = blockIdx.y;
    const int b = bh >> 4, h = bh & 15;

    const float gamma = 1.f / (1.f + expf(-decay[h]));
    const float alpha = expf(log_alpha[h]);
    if (tid < 64) sgp[tid] = powf(gamma, (float)tid);

    const int t0 = chunk * 64;
    const float* basep = outp + (size_t)b*Tt*Dd + h*64;
    const float* vbase = vbuf + (size_t)b*Tt*Dd + h*64;

#pragma unroll
    for (int i = 0; i < 4; i++) {
        int idx = tid + i*256;
        int c = idx >> 4;
        int d4 = (idx & 15) << 2;
        const float* p = basep + (size_t)(t0 + c)*Dd + d4;
        float4 rv = *(const float4*)p;
        sRK[c*SMP + d4+0] = rv.x; sRK[c*SMP + d4+1] = rv.y;
        sRK[c*SMP + d4+2] = rv.z; sRK[c*SMP + d4+3] = rv.w;
        float4 vv = *(const float4*)(vbase + (size_t)(t0 + c)*Dd + d4);
        sV[c*SMP + d4+0] = vv.x; sV[c*SMP + d4+1] = vv.y;
        sV[c*SMP + d4+2] = vv.z; sV[c*SMP + d4+3] = vv.w;
        float4 wv;
        if (t0 + c == 0) wv = make_float4(0.f,0.f,0.f,0.f);
        else             wv = *(const float4*)(p - Dd);
        sWK[c*SMP + d4+0] = wv.x; sWK[c*SMP + d4+1] = wv.y;
        sWK[c*SMP + d4+2] = wv.z; sWK[c*SMP + d4+3] = wv.w;
    }
    __syncthreads();

    const int ty = tid >> 4, tx = tid & 15;
    const int r0 = ty*4, c0 = tx*4;

    // S = masked rk @ wk^T
    {
        float a4[4][4];
#pragma unroll
        for (int i = 0; i < 4; i++)
#pragma unroll
            for (int j = 0; j < 4; j++) a4[i][j] = 0.f;
#pragma unroll 8
        for (int d = 0; d < 64; d++) {
            float a[4], wv[4];
#pragma unroll
            for (int i = 0; i < 4; i++) a[i] = sRK[(r0+i)*SMP + d];
#pragma unroll
            for (int j = 0; j < 4; j++) wv[j] = sWK[(c0+j)*SMP + d];
#pragma unroll
            for (int i = 0; i < 4; i++)
#pragma unroll
                for (int j = 0; j < 4; j++) a4[i][j] += a[i]*wv[j];
        }
#pragma unroll
        for (int i = 0; i < 4; i++) {
            int cc = r0 + i;
#pragma unroll
            for (int j = 0; j < 4; j++) {
                int kk = c0 + j;
                float m = (cc > kk) ? sgp[cc - 1 - kk] : 0.f;
                sS[cc*SMP + kk] = a4[i][j] * m;
            }
        }
    }

    // Z = (v*g_w)^T @ wk
    {
        float z[4][4];
#pragma unroll
        for (int i = 0; i < 4; i++)
#pragma unroll
            for (int j = 0; j < 4; j++) z[i][j] = 0.f;
#pragma unroll 8
        for (int c = 0; c < 64; c++) {
            float gw = sgp[63 - c];
            float a[4], wv[4];
#pragma unroll
            for (int i = 0; i < 4; i++) a[i] = sV[c*SMP + r0 + i] * gw;
#pragma unroll
            for (int j = 0; j < 4; j++) wv[j] = sWK[c*SMP + c0 + j];
#pragma unroll
            for (int i = 0; i < 4; i++)
#pragma unroll
                for (int j = 0; j < 4; j++) z[i][j] += a[i]*wv[j];
        }
        float* zbase = ZW + ((size_t)bh*nCh + chunk)*4096;
#pragma unroll
        for (int i = 0; i < 4; i++)
            *(float4*)&zbase[(r0+i)*64 + c0] =
                make_float4(z[i][0], z[i][1], z[i][2], z[i][3]);
    }
    __syncthreads();

    // intra = alpha * S @ v
    {
        float r[4][4];
#pragma unroll
        for (int i = 0; i < 4; i++)
#pragma unroll
            for (int j = 0; j < 4; j++) r[i][j] = 0.f;
#pragma unroll 8
        for (int k = 0; k < 64; k++) {
            float s[4], vv[4];
#pragma unroll
            for (int i = 0; i < 4; i++) s[i] = sS[(r0+i)*SMP + k];
#pragma unroll
            for (int j = 0; j < 4; j++) vv[j] = sV[k*SMP + c0 + j];
#pragma unroll
            for (int i = 0; i < 4; i++)
#pragma unroll
                for (int j = 0; j < 4; j++) r[i][j] += s[i]*vv[j];
        }
        float* rbase = intra + (size_t)b*Tt*Dd + h*64;
#pragma unroll
        for (int i = 0; i < 4; i++)
            *(float4*)&rbase[(size_t)(t0 + r0 + i)*Dd + c0] =
                make_float4(alpha*r[i][0], alpha*r[i][1],
                            alpha*r[i][2], alpha*r[i][3]);
    }
}

// ===========================================================================
// Scan phase B: in-place exclusive decayed prefix over chunks
// ===========================================================================
__global__ __launch_bounds__(256) void scan_phaseB(
    const float* __restrict__ decay, float* __restrict__ ZW)
{
    const int bh = blockIdx.y, h = bh & 15;
    const int e = blockIdx.x * 256 + threadIdx.x;
    const float gamma = 1.f / (1.f + expf(-decay[h]));
    const float gC = powf(gamma, 64.f);
    float wacc = 0.f;
    size_t base = (size_t)bh*nCh*4096 + e;
#pragma unroll 4
    for (int n = 0; n < nCh; n++) {
        float z = ZW[base + (size_t)n*4096];
        ZW[base + (size_t)n*4096] = wacc;
        wacc = gC*wacc + z;
    }
}

// ===========================================================================
// Scan phase C: inter = g_p * rk @ W^T; reads_h = fp16(intra + alpha*inter)
// ===========================================================================
__global__ __launch_bounds__(256) void scan_phaseC(
    const float* __restrict__ outp,
    const float* __restrict__ decay,
    const float* __restrict__ log_alpha,
    const float* __restrict__ ZW,
    const float* __restrict__ intra,
    __half* __restrict__ reads_h)
{
    float* sRK = gsm;
    float* sW  = sRK + 64*SMP;
    float* sgp = sW  + 64*SMP;

    const int tid = threadIdx.x;
    const int chunk = blockIdx.x;
    const int bh = blockIdx.y;
    const int b = bh >> 4, h = bh & 15;

    const float gamma = 1.f / (1.f + expf(-decay[h]));
    const float alpha = expf(log_alpha[h]);
    if (tid < 64) sgp[tid] = powf(gamma, (float)tid);

    const int t0 = chunk * 64;
    const float* basep = outp + (size_t)b*Tt*Dd + h*64;
    const float* wsrc = ZW + ((size_t)bh*nCh + chunk)*4096;

#pragma unroll
    for (int i = 0; i < 4; i++) {
        int idx = tid + i*256;
        int c = idx >> 4;
        int d4 = (idx & 15) << 2;
        float4 rv = *(const float4*)(basep + (size_t)(t0 + c)*Dd + d4);
        sRK[c*SMP + d4+0] = rv.x; sRK[c*SMP + d4+1] = rv.y;
        sRK[c*SMP + d4+2] = rv.z; sRK[c*SMP + d4+3] = rv.w;
        float4 wv = *(const float4*)(wsrc + c*64 + d4);
        sW[c*SMP + d4+0] = wv.x; sW[c*SMP + d4+1] = wv.y;
        sW[c*SMP + d4+2] = wv.z; sW[c*SMP + d4+3] = wv.w;
    }
    __syncthreads();

    const int ty = tid >> 4, tx = tid & 15;
    const int r0 = ty*4, c0 = tx*4;

    float r[4][4];
#pragma unroll
    for (int i = 0; i < 4; i++)
#pragma unroll
        for (int j = 0; j < 4; j++) r[i][j] = 0.f;
#pragma unroll 8
    for (int j = 0; j < 64; j++) {
        float a[4], wv[4];
#pragma unroll
        for (int i = 0; i < 4; i++) a[i] = sRK[(r0+i)*SMP + j];
#pragma unroll
        for (int jd = 0; jd < 4; jd++) wv[jd] = sW[(c0+jd)*SMP + j];
#pragma unroll
        for (int i = 0; i < 4; i++)
#pragma unroll
            for (int jd = 0; jd < 4; jd++) r[i][jd] += a[i]*wv[jd];
    }

    const float* ibase = intra + (size_t)b*Tt*Dd + h*64;
    __half* hbase = reads_h + (size_t)b*Tt*Dd + h*64;
#pragma unroll
    for (int i = 0; i < 4; i++) {
        float gp = alpha * sgp[r0 + i];
        float4 cur = *(const float4*)&ibase[(size_t)(t0 + r0 + i)*Dd + c0];
        cur.x += gp * r[i][0];
        cur.y += gp * r[i][1];
        cur.z += gp * r[i][2];
        cur.w += gp * r[i][3];
        __half2 h0 = __floats2half2_rn(cur.x, cur.y);
        __half2 h1 = __floats2half2_rn(cur.z, cur.w);
        __half2* hp = (__half2*)&hbase[(size_t)(t0 + r0 + i)*Dd + c0];
        hp[0] = h0; hp[1] = h1;
    }
}

// ===========================================================================
extern "C" void kernel_launch(void* const* d_in, const int* in_sizes, int n_in,
                              void* d_out, int out_size)
{
    const float* outp      = (const float*)d_in[0];
    const float* W_write   = (const float*)d_in[1];
    const float* W_read    = (const float*)d_in[2];
    const float* decay     = (const float*)d_in[3];
    const float* log_alpha = (const float*)d_in[4];
    float* result = (float*)d_out;

    float *vptr, *iptr, *zwptr;
    __half *outh, *wwh, *wrh, *readsh;
    cudaGetSymbolAddress((void**)&vptr, g_v);
    cudaGetSymbolAddress((void**)&iptr, g_intra);
    cudaGetSymbolAddress((void**)&zwptr, g_ZW);
    cudaGetSymbolAddress((void**)&outh, g_out_h);
    cudaGetSymbolAddress((void**)&wwh, g_Ww_h);
    cudaGetSymbolAddress((void**)&wrh, g_Wr_h);
    cudaGetSymbolAddress((void**)&readsh, g_reads_h);

    cudaFuncSetAttribute(h16_gemm_nt,
        cudaFuncAttributeMaxDynamicSharedMemorySize, GEMM_SMEM);
    cudaFuncSetAttribute(scan_phaseA,
        cudaFuncAttributeMaxDynamicSharedMemorySize, A_SMEM);
    cudaFuncSetAttribute(scan_phaseC,
        cudaFuncAttributeMaxDynamicSharedMemorySize, C_SMEM);

    // conversions
    cvt_f2h<<<(Bb*Tt*Dd/4 + 255)/256, 256>>>((const float4*)outp, (__half2*)outh, Bb*Tt*Dd/4);
    cvt_f2h<<<(Dd*Dd/4 + 255)/256, 256>>>((const float4*)W_write, (__half2*)wwh, Dd*Dd/4);
    cvt_f2h<<<(Dd*Dd/4 + 255)/256, 256>>>((const float4*)W_read, (__half2*)wrh, Dd*Dd/4);

    dim3 gemm_grid(Dd/128, Mrows/128);   // (8, 128)

    // GEMM1: v = out @ W_write^T  (fp16 in, fp32 out)
    h16_gemm_nt<<<gemm_grid, 256, GEMM_SMEM>>>(outh, wwh, nullptr, vptr,
                                               Mrows, Dd, Dd, 0);
    // Scan
    scan_phaseA<<<dim3(nCh, BHt), 256, A_SMEM>>>(outp, vptr, decay, log_alpha,
                                                 iptr, zwptr);
    scan_phaseB<<<dim3(16, BHt), 256>>>(decay, zwptr);
    scan_phaseC<<<dim3(nCh, BHt), 256, C_SMEM>>>(outp, decay, log_alpha,
                                                 zwptr, iptr, readsh);
    // GEMM2: result = out + reads @ W_read^T
    h16_gemm_nt<<<gemm_grid, 256, GEMM_SMEM>>>(readsh, wrh, outp, result,
                                               Mrows, Dd, Dd, 1);
}

// round 4
// speedup vs baseline: 6.8623x; 1.8117x over previous
#include <cuda_runtime.h>
#include <cuda_fp16.h>
#include <cstdint>

// Problem constants
#define Bb 4
#define Tt 4096
#define Dd 1024
#define Hh 16
#define Cc 64
#define nCh 64
#define BHt 64
#define Mrows (Bb*Tt)   // 16384

// Scratch (__device__ globals per allocation rules)
__device__ __half g_out_h[Bb*Tt*Dd];     // fp16 input
__device__ __half g_Ww_h[Dd*Dd];
__device__ __half g_Wr_h[Dd*Dd];
__device__ __half g_v_h[Bb*Tt*Dd];       // fp16 write projection
__device__ float  g_intra[Bb*Tt*Dd];     // alpha*intra fp32
__device__ float  g_ZW[BHt*nCh*64*64];   // fp32 chunk increments Z
__device__ __half g_W_h[BHt*nCh*64*64];  // fp16 per-chunk W states
__device__ __half g_reads_h[Bb*Tt*Dd];   // fp16 reads (GEMM2 A)

extern __shared__ float gsm[];

// ---------------------------------------------------------------------------
// helpers
// ---------------------------------------------------------------------------
__device__ __forceinline__ void cp16g(void* sdst, const void* gsrc) {
    unsigned s = (unsigned)__cvta_generic_to_shared(sdst);
    asm volatile("cp.async.ca.shared.global [%0], [%1], 16;" :: "r"(s), "l"(gsrc));
}
__device__ __forceinline__ void ldsm4(uint32_t addr, uint32_t& r0, uint32_t& r1,
                                      uint32_t& r2, uint32_t& r3) {
    asm volatile("ldmatrix.sync.aligned.m8n8.x4.shared.b16 {%0,%1,%2,%3}, [%4];"
        : "=r"(r0), "=r"(r1), "=r"(r2), "=r"(r3) : "r"(addr));
}
__device__ __forceinline__ void ldsm4t(uint32_t addr, uint32_t& r0, uint32_t& r1,
                                       uint32_t& r2, uint32_t& r3) {
    asm volatile("ldmatrix.sync.aligned.m8n8.x4.trans.shared.b16 {%0,%1,%2,%3}, [%4];"
        : "=r"(r0), "=r"(r1), "=r"(r2), "=r"(r3) : "r"(addr));
}
__device__ __forceinline__ void mma_f16(float c[4], uint32_t a0, uint32_t a1,
                                        uint32_t a2, uint32_t a3,
                                        uint32_t b0, uint32_t b1) {
    asm volatile(
        "mma.sync.aligned.m16n8k16.row.col.f32.f16.f16.f32 "
        "{%0,%1,%2,%3}, {%4,%5,%6,%7}, {%8,%9}, {%0,%1,%2,%3};"
        : "+f"(c[0]), "+f"(c[1]), "+f"(c[2]), "+f"(c[3])
        : "r"(a0), "r"(a1), "r"(a2), "r"(a3), "r"(b0), "r"(b1));
}

// ---------------------------------------------------------------------------
// fp32 -> fp16 conversion
// ---------------------------------------------------------------------------
__global__ __launch_bounds__(256) void cvt_f2h(
    const float4* __restrict__ src, __half2* __restrict__ dst, int n4)
{
    int i = blockIdx.x * blockDim.x + threadIdx.x;
    if (i < n4) {
        float4 v = src[i];
        dst[i*2]   = __floats2half2_rn(v.x, v.y);
        dst[i*2+1] = __floats2half2_rn(v.z, v.w);
    }
}

// ===========================================================================
// fp16 tensor-core GEMM (NT): C[m,n]=sum_k A[m,k]*B[n,k] (+Cin fp32).
// outHalf: write fp16 result instead of fp32.
// ===========================================================================
#define HSTR 40
#define HSTAGE (128*HSTR)
#define GEMM_SMEM (3*2*HSTAGE*(int)sizeof(__half))

__global__ __launch_bounds__(256, 2) void h16_gemm_nt(
    const __half* __restrict__ A,
    const __half* __restrict__ B,
    const float* __restrict__ Cin,
    void* __restrict__ CoutV,
    int M, int N, int K, int addC, int outHalf)
{
    __half* hsm = (__half*)gsm;
    const int tid  = threadIdx.x;
    const int lane = tid & 31;
    const int w    = tid >> 5;
    const int wm   = w >> 2;
    const int wn   = w & 3;
    const int gid  = lane >> 2;
    const int t4   = lane & 3;

    const int bm = blockIdx.y * 128;
    const int bn = blockIdx.x * 128;
    const uint32_t sb = (uint32_t)__cvta_generic_to_shared(hsm);

    float acc[4][4][4];
#pragma unroll
    for (int i = 0; i < 4; i++)
#pragma unroll
        for (int j = 0; j < 4; j++)
#pragma unroll
            for (int q = 0; q < 4; q++) acc[i][j][q] = 0.f;

    const int NIT = K / 32;

    auto copy_stage = [&](int it, int st) {
        const int kt = it * 32;
        __half* ad = hsm + st * HSTAGE;
        __half* bd = hsm + 3 * HSTAGE + st * HSTAGE;
#pragma unroll
        for (int i = 0; i < 2; i++) {
            int ch = tid + i * 256;
            int r  = ch >> 2;
            int c  = (ch & 3) * 8;
            cp16g(ad + r * HSTR + c, A + (size_t)(bm + r) * K + kt + c);
            cp16g(bd + r * HSTR + c, B + (size_t)(bn + r) * K + kt + c);
        }
    };

    copy_stage(0, 0);
    asm volatile("cp.async.commit_group;");
    copy_stage(1, 1);
    asm volatile("cp.async.commit_group;");

    const int lrow = lane & 15;
    const int lcol = (lane >> 4) * 8;

    for (int it = 0; it < NIT; it++) {
        asm volatile("cp.async.wait_group 1;");
        __syncthreads();
        const int st = it % 3;
        const uint32_t abase = sb + (st * HSTAGE) * 2;
        const uint32_t bbase = sb + (3 * HSTAGE + st * HSTAGE) * 2;

#pragma unroll
        for (int kk = 0; kk < 2; kk++) {
            const int k0 = kk * 16;
            uint32_t af[4][4], bf[4][2];
#pragma unroll
            for (int i = 0; i < 4; i++)
                ldsm4(abase + ((wm*64 + i*16 + lrow) * HSTR + k0 + lcol) * 2,
                      af[i][0], af[i][1], af[i][2], af[i][3]);
#pragma unroll
            for (int p = 0; p < 2; p++) {
                uint32_t r0, r1, r2, r3;
                ldsm4(bbase + ((wn*32 + p*16 + lrow) * HSTR + k0 + lcol) * 2,
                      r0, r1, r2, r3);
                bf[2*p  ][0] = r0; bf[2*p+1][0] = r1;
                bf[2*p  ][1] = r2; bf[2*p+1][1] = r3;
            }
#pragma unroll
            for (int i = 0; i < 4; i++)
#pragma unroll
                for (int j = 0; j < 4; j++)
                    mma_f16(acc[i][j], af[i][0], af[i][1], af[i][2], af[i][3],
                            bf[j][0], bf[j][1]);
        }
        if (it + 2 < NIT) copy_stage(it + 2, (it + 2) % 3);
        asm volatile("cp.async.commit_group;");
    }

#pragma unroll
    for (int i = 0; i < 4; i++) {
        int row = bm + wm*64 + i*16 + gid;
#pragma unroll
        for (int j = 0; j < 4; j++) {
            int col = bn + wn*32 + j*8 + t4*2;
            float2 r01 = make_float2(acc[i][j][0], acc[i][j][1]);
            float2 r23 = make_float2(acc[i][j][2], acc[i][j][3]);
            if (addC) {
                float2 c01 = *(const float2*)&Cin[(size_t)row*N + col];
                float2 c23 = *(const float2*)&Cin[(size_t)(row+8)*N + col];
                r01.x += c01.x; r01.y += c01.y;
                r23.x += c23.x; r23.y += c23.y;
            }
            if (outHalf) {
                __half* Ch = (__half*)CoutV;
                *(__half2*)&Ch[(size_t)row*N + col]     = __floats2half2_rn(r01.x, r01.y);
                *(__half2*)&Ch[(size_t)(row+8)*N + col] = __floats2half2_rn(r23.x, r23.y);
            } else {
                float* Cf = (float*)CoutV;
                *(float2*)&Cf[(size_t)row*N + col]     = r01;
                *(float2*)&Cf[(size_t)(row+8)*N + col] = r23;
            }
        }
    }
}

// ===========================================================================
// Scan phase A (tensor cores, 128 thr = 4 warps, warp w owns rows 16w..16w+15)
//   S = (rk @ wk^T) * mask  (fp16 in smem)
//   intra = alpha * S @ v        -> g_intra (fp32)
//   Z = (v*g_w)^T @ wk           -> g_ZW (fp32)
// ===========================================================================
#define TSTR 72
#define PA_SMEM (4*64*TSTR*2 + 64*4)
#define PC_SMEM (2*64*TSTR*2 + 64*4)

__global__ __launch_bounds__(128) void scan_phaseA_mma(
    const __half* __restrict__ outh, const __half* __restrict__ vh,
    const float* __restrict__ decay, const float* __restrict__ log_alpha,
    float* __restrict__ intra, float* __restrict__ ZW)
{
    __half* sRK = (__half*)gsm;            // later reused as vg
    __half* sWK = sRK + 64*TSTR;
    __half* sV  = sWK + 64*TSTR;
    __half* sS  = sV  + 64*TSTR;
    float*  sgp = (float*)(sS + 64*TSTR);

    const int tid = threadIdx.x, lane = tid & 31, w = tid >> 5;
    const int chunk = blockIdx.x, bh = blockIdx.y;
    const int b = bh >> 4, h = bh & 15;
    const float gamma = 1.f/(1.f+expf(-decay[h]));
    const float alpha = expf(log_alpha[h]);
    if (tid < 64) sgp[tid] = powf(gamma, (float)tid);

    const int t0 = chunk*64;
    const __half* rbase = outh + ((size_t)b*Tt + t0)*Dd + h*64;
    const __half* vbase = vh   + ((size_t)b*Tt + t0)*Dd + h*64;

#pragma unroll
    for (int i = 0; i < 4; i++) {
        int idx = tid + i*128;
        int r = idx >> 3;
        int c8 = (idx & 7)*8;
        cp16g(sRK + r*TSTR + c8, rbase + (size_t)r*Dd + c8);
        cp16g(sV  + r*TSTR + c8, vbase + (size_t)r*Dd + c8);
        long wr = (t0 + r == 0) ? 0 : (long)(r - 1);
        cp16g(sWK + r*TSTR + c8, rbase + wr*(long)Dd + c8);
    }
    asm volatile("cp.async.commit_group;");
    asm volatile("cp.async.wait_group 0;");
    __syncthreads();
    if (chunk == 0 && tid < 8)
        *(uint4*)(sWK + tid*8) = make_uint4(0u,0u,0u,0u);
    __syncthreads();

    const uint32_t sb  = (uint32_t)__cvta_generic_to_shared((void*)sRK);
    const uint32_t aRK = sb;
    const uint32_t aWK = sb + 64*TSTR*2;
    const uint32_t aV  = sb + 2*64*TSTR*2;
    const uint32_t aS  = sb + 3*64*TSTR*2;

    const int lr = lane & 15;
    const int lc = (lane >> 4) * 8;
    const int trr = (lane & 7) + 8*(lane >> 4);  // trans row offset
    const int trc = 8*((lane >> 3) & 1);         // trans col offset
    const int gid = lane >> 2, t4 = lane & 3;
    const int cc0 = 16*w + gid;

    // ---- S = rk @ wk^T ----
    {
        float acc[8][4];
#pragma unroll
        for (int n = 0; n < 8; n++)
            acc[n][0]=acc[n][1]=acc[n][2]=acc[n][3]=0.f;
#pragma unroll
        for (int k = 0; k < 4; k++) {
            int k0 = k*16;
            uint32_t a0,a1,a2,a3;
            ldsm4(aRK + ((16*w + lr)*TSTR + k0 + lc)*2, a0,a1,a2,a3);
#pragma unroll
            for (int np = 0; np < 4; np++) {
                uint32_t b0,b1,b2,b3;
                ldsm4(aWK + ((np*16 + lr)*TSTR + k0 + lc)*2, b0,b1,b2,b3);
                mma_f16(acc[2*np],   a0,a1,a2,a3, b0,b2);
                mma_f16(acc[2*np+1], a0,a1,a2,a3, b1,b3);
            }
        }
        // apply mask, store fp16 S
#pragma unroll
        for (int nt = 0; nt < 8; nt++) {
            int kk = nt*8 + 2*t4;
            float m00 = (cc0   > kk  ) ? sgp[cc0-1-kk] : 0.f;
            float m01 = (cc0   > kk+1) ? sgp[cc0-2-kk] : 0.f;
            float m10 = (cc0+8 > kk  ) ? sgp[cc0+7-kk] : 0.f;
            float m11 = (cc0+8 > kk+1) ? sgp[cc0+6-kk] : 0.f;
            *(__half2*)(sS + (size_t)cc0*TSTR + kk) =
                __floats2half2_rn(acc[nt][0]*m00, acc[nt][1]*m01);
            *(__half2*)(sS + (size_t)(cc0+8)*TSTR + kk) =
                __floats2half2_rn(acc[nt][2]*m10, acc[nt][3]*m11);
        }
    }
    __syncthreads();

    // vg[c][i] = v[c][i] * gamma^(63-c)  (overwrite sRK)
#pragma unroll
    for (int i = 0; i < 16; i++) {
        int idx = tid + i*128;
        int row = idx >> 5, col2 = idx & 31;
        __half2 g2 = __float2half2_rn(sgp[63 - row]);
        ((__half2*)sRK)[row*(TSTR/2) + col2] =
            __hmul2(((__half2*)sV)[row*(TSTR/2) + col2], g2);
    }
    __syncthreads();

    // ---- intra = S @ v  (B = v^T via ldmatrix.trans) ----
    {
        float iacc[8][4];
#pragma unroll
        for (int n = 0; n < 8; n++)
            iacc[n][0]=iacc[n][1]=iacc[n][2]=iacc[n][3]=0.f;
#pragma unroll
        for (int k = 0; k < 4; k++) {
            int k0 = k*16;
            uint32_t a0,a1,a2,a3;
            ldsm4(aS + ((16*w + lr)*TSTR + k0 + lc)*2, a0,a1,a2,a3);
#pragma unroll
            for (int np = 0; np < 4; np++) {
                uint32_t b0,b1,b2,b3;
                ldsm4t(aV + ((k0 + trr)*TSTR + np*16 + trc)*2, b0,b1,b2,b3);
                mma_f16(iacc[2*np],   a0,a1,a2,a3, b0,b2);
                mma_f16(iacc[2*np+1], a0,a1,a2,a3, b1,b3);
            }
        }
        float* ibase = intra + ((size_t)b*Tt + t0)*Dd + h*64;
#pragma unroll
        for (int nt = 0; nt < 8; nt++) {
            int col = nt*8 + 2*t4;
            *(float2*)&ibase[(size_t)cc0*Dd + col] =
                make_float2(alpha*iacc[nt][0], alpha*iacc[nt][1]);
            *(float2*)&ibase[(size_t)(cc0+8)*Dd + col] =
                make_float2(alpha*iacc[nt][2], alpha*iacc[nt][3]);
        }
    }

    // ---- Z = vg^T @ wk  (A trans, B trans) ----
    {
        float zacc[8][4];
#pragma unroll
        for (int n = 0; n < 8; n++)
            zacc[n][0]=zacc[n][1]=zacc[n][2]=zacc[n][3]=0.f;
#pragma unroll
        for (int k = 0; k < 4; k++) {
            int k0 = k*16;
            uint32_t a0,a1,a2,a3;
            ldsm4t(aRK + ((k0 + trr)*TSTR + 16*w + trc)*2, a0,a1,a2,a3);
#pragma unroll
            for (int np = 0; np < 4; np++) {
                uint32_t b0,b1,b2,b3;
                ldsm4t(aWK + ((k0 + trr)*TSTR + np*16 + trc)*2, b0,b1,b2,b3);
                mma_f16(zacc[2*np],   a0,a1,a2,a3, b0,b2);
                mma_f16(zacc[2*np+1], a0,a1,a2,a3, b1,b3);
            }
        }
        float* zbase = ZW + ((size_t)bh*nCh + chunk)*4096;
#pragma unroll
        for (int nt = 0; nt < 8; nt++) {
            int col = nt*8 + 2*t4;
            *(float2*)&zbase[cc0*64 + col] =
                make_float2(zacc[nt][0], zacc[nt][1]);
            *(float2*)&zbase[(cc0+8)*64 + col] =
                make_float2(zacc[nt][2], zacc[nt][3]);
        }
    }
}

// ===========================================================================
// Scan phase B: decayed exclusive prefix over chunks; emit fp16 W states.
// ===========================================================================
__global__ __launch_bounds__(256) void scan_phaseB(
    const float* __restrict__ decay, const float* __restrict__ ZW,
    __half* __restrict__ Wh)
{
    const int bh = blockIdx.y, h = bh & 15;
    const int e = blockIdx.x * 256 + threadIdx.x;
    const float gamma = 1.f/(1.f+expf(-decay[h]));
    const float gC = powf(gamma, 64.f);
    float wacc = 0.f;
    size_t base = (size_t)bh*nCh*4096 + e;
#pragma unroll 4
    for (int n = 0; n < nCh; n++) {
        float z = ZW[base + (size_t)n*4096];
        Wh[base + (size_t)n*4096] = __float2half(wacc);
        wacc = gC*wacc + z;
    }
}

// ===========================================================================
// Scan phase C (tensor cores): inter = rk @ W^T;
//   reads_h = fp16(intra + alpha*g_p[c]*inter)
// ===========================================================================
__global__ __launch_bounds__(128) void scan_phaseC_mma(
    const __half* __restrict__ outh, const __half* __restrict__ Wh,
    const float* __restrict__ decay, const float* __restrict__ log_alpha,
    const float* __restrict__ intra, __half* __restrict__ readsh)
{
    __half* sRK = (__half*)gsm;
    __half* sW  = sRK + 64*TSTR;
    float*  sgp = (float*)(sW + 64*TSTR);

    const int tid = threadIdx.x, lane = tid & 31, w = tid >> 5;
    const int chunk = blockIdx.x, bh = blockIdx.y;
    const int b = bh >> 4, h = bh & 15;
    const float gamma = 1.f/(1.f+expf(-decay[h]));
    const float alpha = expf(log_alpha[h]);
    if (tid < 64) sgp[tid] = powf(gamma, (float)tid);

    const int t0 = chunk*64;
    const __half* rbase = outh + ((size_t)b*Tt + t0)*Dd + h*64;
    const __half* wsrc  = Wh + ((size_t)bh*nCh + chunk)*4096;

#pragma unroll
    for (int i = 0; i < 4; i++) {
        int idx = tid + i*128;
        int r = idx >> 3;
        int c8 = (idx & 7)*8;
        cp16g(sRK + r*TSTR + c8, rbase + (size_t)r*Dd + c8);
        cp16g(sW  + r*TSTR + c8, wsrc + r*64 + c8);
    }
    asm volatile("cp.async.commit_group;");
    asm volatile("cp.async.wait_group 0;");
    __syncthreads();

    const uint32_t sb  = (uint32_t)__cvta_generic_to_shared((void*)sRK);
    const uint32_t aRK = sb;
    const uint32_t aW  = sb + 64*TSTR*2;

    const int lr = lane & 15;
    const int lc = (lane >> 4) * 8;
    const int gid = lane >> 2, t4 = lane & 3;
    const int cc0 = 16*w + gid;

    float acc[8][4];
#pragma unroll
    for (int n = 0; n < 8; n++)
        acc[n][0]=acc[n][1]=acc[n][2]=acc[n][3]=0.f;
#pragma unroll
    for (int k = 0; k < 4; k++) {
        int k0 = k*16;
        uint32_t a0,a1,a2,a3;
        ldsm4(aRK + ((16*w + lr)*TSTR + k0 + lc)*2, a0,a1,a2,a3);
#pragma unroll
        for (int np = 0; np < 4; np++) {
            uint32_t b0,b1,b2,b3;
            ldsm4(aW + ((np*16 + lr)*TSTR + k0 + lc)*2, b0,b1,b2,b3);
            mma_f16(acc[2*np],   a0,a1,a2,a3, b0,b2);
            mma_f16(acc[2*np+1], a0,a1,a2,a3, b1,b3);
        }
    }

    const float* ibase = intra + ((size_t)b*Tt + t0)*Dd + h*64;
    __half* obase = readsh + ((size_t)b*Tt + t0)*Dd + h*64;
    const float gp0 = alpha * sgp[cc0];
    const float gp1 = alpha * sgp[cc0 + 8];
#pragma unroll
    for (int nt = 0; nt < 8; nt++) {
        int col = nt*8 + 2*t4;
        float2 i0 = *(const float2*)&ibase[(size_t)cc0*Dd + col];
        float2 i1 = *(const float2*)&ibase[(size_t)(cc0+8)*Dd + col];
        *(__half2*)&obase[(size_t)cc0*Dd + col] =
            __floats2half2_rn(i0.x + gp0*acc[nt][0], i0.y + gp0*acc[nt][1]);
        *(__half2*)&obase[(size_t)(cc0+8)*Dd + col] =
            __floats2half2_rn(i1.x + gp1*acc[nt][2], i1.y + gp1*acc[nt][3]);
    }
}

// ===========================================================================
extern "C" void kernel_launch(void* const* d_in, const int* in_sizes, int n_in,
                              void* d_out, int out_size)
{
    const float* outp      = (const float*)d_in[0];
    const float* W_write   = (const float*)d_in[1];
    const float* W_read    = (const float*)d_in[2];
    const float* decay     = (const float*)d_in[3];
    const float* log_alpha = (const float*)d_in[4];
    float* result = (float*)d_out;

    __half *outh, *wwh, *wrh, *vh, *whs, *readsh;
    float *iptr, *zwptr;
    cudaGetSymbolAddress((void**)&outh,   g_out_h);
    cudaGetSymbolAddress((void**)&wwh,    g_Ww_h);
    cudaGetSymbolAddress((void**)&wrh,    g_Wr_h);
    cudaGetSymbolAddress((void**)&vh,     g_v_h);
    cudaGetSymbolAddress((void**)&iptr,   g_intra);
    cudaGetSymbolAddress((void**)&zwptr,  g_ZW);
    cudaGetSymbolAddress((void**)&whs,    g_W_h);
    cudaGetSymbolAddress((void**)&readsh, g_reads_h);

    cudaFuncSetAttribute(h16_gemm_nt,
        cudaFuncAttributeMaxDynamicSharedMemorySize, GEMM_SMEM);
    cudaFuncSetAttribute(scan_phaseA_mma,
        cudaFuncAttributeMaxDynamicSharedMemorySize, PA_SMEM);
    cudaFuncSetAttribute(scan_phaseC_mma,
        cudaFuncAttributeMaxDynamicSharedMemorySize, PC_SMEM);

    // conversions
    cvt_f2h<<<(Bb*Tt*Dd/4 + 255)/256, 256>>>((const float4*)outp, (__half2*)outh, Bb*Tt*Dd/4);
    cvt_f2h<<<(Dd*Dd/4 + 255)/256, 256>>>((const float4*)W_write, (__half2*)wwh, Dd*Dd/4);
    cvt_f2h<<<(Dd*Dd/4 + 255)/256, 256>>>((const float4*)W_read, (__half2*)wrh, Dd*Dd/4);

    dim3 gemm_grid(Dd/128, Mrows/128);

    // GEMM1: v_h = fp16(out @ W_write^T)
    h16_gemm_nt<<<gemm_grid, 256, GEMM_SMEM>>>(outh, wwh, nullptr, vh,
                                               Mrows, Dd, Dd, 0, 1);
    // Scan
    scan_phaseA_mma<<<dim3(nCh, BHt), 128, PA_SMEM>>>(outh, vh, decay, log_alpha,
                                                      iptr, zwptr);
    scan_phaseB<<<dim3(16, BHt), 256>>>(decay, zwptr, whs);
    scan_phaseC_mma<<<dim3(nCh, BHt), 128, PC_SMEM>>>(outh, whs, decay, log_alpha,
                                                      iptr, readsh);
    // GEMM2: result = out + reads @ W_read^T (fp32 out)
    h16_gemm_nt<<<gemm_grid, 256, GEMM_SMEM>>>(readsh, wrh, outp, result,
                                               Mrows, Dd, Dd, 1, 0);
}